// round 11
// baseline (speedup 1.0000x reference)
#include <cuda_runtime.h>

// ----------------------------------------------------------------------------
// Cross_MultiAttention — algebraically folded, dual-lane (branch-pair) f32x2.
//
// logit_h,br(s,j) = (f_br[s] @ M_h + v_h) . fcat[j]    (M_h [6,12])
// att@V folds through Wp into per-(head,branch) [6,12] P.
// fcat stored ONCE in smem lane-duplicated (f_c,f_c); per head, g packs the
// two branches in the f32x2 lanes, so the 12-term dot yields (l1,l2) with no
// horizontal adds, and one dual G[12] accumulates both branches.
// 26 fma-pipe slots per (j,head); no per-pass smem writes; unroll 4; 2 CTA/SM.
// ----------------------------------------------------------------------------

#define SCALE_EMB 0.044194173824159216f   // 512^-0.5
#define LOG2E     1.4426950408889634f

typedef unsigned long long u64;

struct Params {
    float M[8][6][12];      // LOG2E*SCALE * A_q_h @ A_k_h^T
    float v[8][12];         // LOG2E*SCALE * bq_eff_h @ A_k_h^T
    u64   Pp[8][6][12];     // pack2(P_br1[h][o][c], P_br2[h][o][c])
    float C[6];             // bp + (Wp1+Wp2) @ bv_eff
};

__device__ float g_part[3][8][13][512];   // per-m-chunk partial folds (row12 = bias)
__device__ float g_A[3][13][512];         // folded: [0]=Aq(6)+bqe, [1]=Ak+bke, [2]=Av+bve
__device__ Params g_params;

// ---- packed f32x2 helpers ----
__device__ __forceinline__ u64 pack2(float lo, float hi) {
    u64 r; asm("mov.b64 %0, {%1,%2};" : "=l"(r) : "f"(lo), "f"(hi)); return r;
}
__device__ __forceinline__ void unpack2(u64 v, float& lo, float& hi) {
    asm("mov.b64 {%0,%1}, %2;" : "=f"(lo), "=f"(hi) : "l"(v));
}
__device__ __forceinline__ u64 fma2(u64 a, u64 b, u64 c) {
    u64 d; asm("fma.rn.f32x2 %0, %1, %2, %3;" : "=l"(d) : "l"(a), "l"(b), "l"(c)); return d;
}
__device__ __forceinline__ u64 mul2(u64 a, u64 b) {
    u64 d; asm("mul.rn.f32x2 %0, %1, %2;" : "=l"(d) : "l"(a), "l"(b)); return d;
}
__device__ __forceinline__ u64 add2(u64 a, u64 b) {
    u64 d; asm("add.rn.f32x2 %0, %1, %2;" : "=l"(d) : "l"(a), "l"(b)); return d;
}
__device__ __forceinline__ float ex2f(float x) {
    float y; asm("ex2.approx.ftz.f32 %0, %1;" : "=f"(y) : "f"(x)); return y;
}
__device__ __forceinline__ float rcpf(float x) {
    float y; asm("rcp.approx.ftz.f32 %0, %1;" : "=f"(y) : "f"(x)); return y;
}

// ----------------------------------------------------------------------------
// Precompute 1a: partial fold over a 64-wide m chunk.
// ----------------------------------------------------------------------------
__global__ void fold_partial(const float* __restrict__ W_emb,  const float* __restrict__ b_emb,
                             const float* __restrict__ W_emb2, const float* __restrict__ b_emb2,
                             const float* __restrict__ Wq, const float* __restrict__ Wk,
                             const float* __restrict__ Wv)
{
    int mat = blockIdx.x >> 3, chunk = blockIdx.x & 7;
    const float* We = (mat == 0) ? W_emb : W_emb2;
    const float* be = (mat == 0) ? b_emb : b_emb2;
    const float* W  = (mat == 0) ? Wq : (mat == 1 ? Wk : Wv);
    int R = (mat == 0) ? 6 : 12;

    __shared__ float sE[12][64];
    __shared__ float sb[64];
    int tid = threadIdx.x;
    int mc0 = chunk * 64;
    for (int i = tid; i < R * 64; i += 512) {
        int k = i >> 6, mm = i & 63;
        sE[k][mm] = We[k * 512 + mc0 + mm];
    }
    if (tid < 64) sb[tid] = be[mc0 + tid];
    __syncthreads();

    int e = tid;
    float acc[12];
#pragma unroll
    for (int k = 0; k < 12; k++) acc[k] = 0.f;
    float bacc = 0.f;
    if (R == 6) {
#pragma unroll 8
        for (int mm = 0; mm < 64; mm++) {
            float w = W[(mc0 + mm) * 512 + e];
            bacc += sb[mm] * w;
#pragma unroll
            for (int k = 0; k < 6; k++) acc[k] += sE[k][mm] * w;
        }
    } else {
#pragma unroll 4
        for (int mm = 0; mm < 64; mm++) {
            float w = W[(mc0 + mm) * 512 + e];
            bacc += sb[mm] * w;
#pragma unroll
            for (int k = 0; k < 12; k++) acc[k] += sE[k][mm] * w;
        }
    }
    for (int k = 0; k < R; k++) g_part[mat][chunk][k][e] = acc[k];
    g_part[mat][chunk][12][e] = bacc;
}

// ----------------------------------------------------------------------------
// Precompute 1b: deterministic reduce over the 8 chunks + add projection bias.
// ----------------------------------------------------------------------------
__global__ void fold_reduce(const float* __restrict__ bq, const float* __restrict__ bk,
                            const float* __restrict__ bv)
{
    int t = blockIdx.x * blockDim.x + threadIdx.x;
    if (t >= 3 * 13 * 512) return;
    int mat = t / (13 * 512);
    int r   = (t / 512) % 13;
    int e   = t & 511;
    if (mat == 0 && r >= 6 && r < 12) { g_A[0][r][e] = 0.f; return; }
    float s = 0.f;
#pragma unroll
    for (int c = 0; c < 8; c++) s += g_part[mat][c][r][e];
    if (r == 12) s += (mat == 0 ? bq[e] : (mat == 1 ? bk[e] : bv[e]));
    g_A[mat][r][e] = s;
}

// ----------------------------------------------------------------------------
// Precompute 2: tiny per-head matrices (log2e*SCALE prefolded; P lane-packed).
// ----------------------------------------------------------------------------
__global__ void precompute_small(const float* __restrict__ Wp, const float* __restrict__ bp)
{
    int idx = blockIdx.x * 256 + threadIdx.x;
    const float KS = LOG2E * SCALE_EMB;
    if (idx < 576) {                                   // M[h][k][c]
        int h = idx / 72, r = idx % 72, k = r / 12, c = r % 12;
        float s = 0.f;
#pragma unroll 4
        for (int d = 0; d < 64; d++) s += g_A[0][k][h * 64 + d] * g_A[1][c][h * 64 + d];
        g_params.M[h][k][c] = KS * s;
    } else if (idx < 672) {                            // v[h][c]
        int t = idx - 576, h = t / 12, c = t % 12;
        float s = 0.f;
#pragma unroll 4
        for (int d = 0; d < 64; d++) s += g_A[0][12][h * 64 + d] * g_A[1][c][h * 64 + d];
        g_params.v[h][c] = KS * s;
    } else if (idx < 1248) {                           // Pp[h][o][c] (both branches)
        int t = idx - 672, h = t / 72, q = t % 72, o = q / 12, c = q % 12;
        float s0 = 0.f, s1 = 0.f;
#pragma unroll 4
        for (int d = 0; d < 64; d++) {
            float av = g_A[2][c][h * 64 + d];
            s0 += Wp[o * 1024 +       h * 64 + d] * av;
            s1 += Wp[o * 1024 + 512 + h * 64 + d] * av;
        }
        g_params.Pp[h][o][c] = pack2(s0, s1);
    } else if (idx < 1254) {                           // C[o]
        int o = idx - 1248;
        float s = bp[o];
#pragma unroll 4
        for (int e = 0; e < 512; e++)
            s += (Wp[o * 1024 + e] + Wp[o * 1024 + 512 + e]) * g_A[2][12][e];
        g_params.C[o] = s;
    }
}

// ----------------------------------------------------------------------------
// Main fused kernel: one CTA per 16x16 tile (512 CTAs), one thread per query s.
// 8 passes (one head, both branches in lanes). Dup-packed fcat: 96B rows,
// 6 LDS.128/j, written once. No syncs/writes inside the pass loop.
// ----------------------------------------------------------------------------
__global__ __launch_bounds__(256, 2)
void cross_attn_main(const float* __restrict__ img1, const float* __restrict__ img2,
                     float* __restrict__ out)
{
    __shared__ __align__(16) u64 sFd[256][12];   // (f_c, f_c) dup-lane
    __shared__ Params sp;

    int b  = blockIdx.x;
    int bi = b >> 6, th = (b >> 3) & 7, tw = b & 7;
    int s  = threadIdx.x;
    int y  = s >> 4, x = s & 15;
    int base = bi * 6 * 16384 + (th * 16 + y) * 128 + (tw * 16 + x);

    {
        float a;
#pragma unroll
        for (int c = 0; c < 6; c++) {
            a = img1[base + c * 16384];
            sFd[s][c] = pack2(a, a);
            a = img2[base + c * 16384];
            sFd[s][6 + c] = pack2(a, a);
        }
    }
    {
        float* dst = (float*)&sp;
        const float* src = (const float*)&g_params;
        for (int i = s; i < (int)(sizeof(Params) / 4); i += 256) dst[i] = src[i];
    }
    __syncthreads();

    u64 outaccD[6];
#pragma unroll
    for (int o = 0; o < 6; o++) outaccD[o] = 0ull;

    for (int h = 0; h < 8; h++) {
        // ---- setup: g[c] = (v+f1@M, v+f2@M) lanes; fc re-read from sFd ----
        u64 g[12];
        {
            float fc[12];
            const ulonglong2* mp = (const ulonglong2*)(&sFd[s][0]);
#pragma unroll
            for (int q = 0; q < 6; q++) {
                ulonglong2 m = mp[q];
                float d0, d1;
                unpack2(m.x, d0, d1); fc[2 * q] = d0;
                unpack2(m.y, d0, d1); fc[2 * q + 1] = d0;
            }
#pragma unroll
            for (int c = 0; c < 12; c++) {
                float a1 = sp.v[h][c], a2 = a1;
#pragma unroll
                for (int k = 0; k < 6; k++) {
                    float m = sp.M[h][k][c];
                    a1 += fc[k] * m;
                    a2 += fc[6 + k] * m;
                }
                g[c] = pack2(a1, a2);
            }
        }

        u64 G[12];
#pragma unroll
        for (int c = 0; c < 12; c++) G[c] = 0ull;
        u64 l12 = 0ull;                 // packed (l1, l2)

        // Logits are O(0.1) by construction (weights 0.02, folded twice):
        // exp without max-subtraction is exact softmax.
#pragma unroll 4
        for (int j = 0; j < 256; j++) {
            const ulonglong2* rp = (const ulonglong2*)(&sFd[j][0]);
            ulonglong2 q0 = rp[0], q1 = rp[1], q2 = rp[2];
            ulonglong2 q3 = rp[3], q4 = rp[4], q5 = rp[5];
            u64 fd0 = q0.x, fd1 = q0.y, fd2  = q1.x, fd3  = q1.y;
            u64 fd4 = q2.x, fd5 = q2.y, fd6  = q3.x, fd7  = q3.y;
            u64 fd8 = q4.x, fd9 = q4.y, fd10 = q5.x, fd11 = q5.y;

            // dual-lane logits: two 6-deep chains, lanes = branches
            u64 ae = mul2(g[0], fd0);
            u64 ao = mul2(g[1], fd1);
            ae = fma2(g[2],  fd2,  ae);  ao = fma2(g[3],  fd3,  ao);
            ae = fma2(g[4],  fd4,  ae);  ao = fma2(g[5],  fd5,  ao);
            ae = fma2(g[6],  fd6,  ae);  ao = fma2(g[7],  fd7,  ao);
            ae = fma2(g[8],  fd8,  ae);  ao = fma2(g[9],  fd9,  ao);
            ae = fma2(g[10], fd10, ae);  ao = fma2(g[11], fd11, ao);
            u64 a = add2(ae, ao);        // (l1_logit, l2_logit)

            float e0, e1;
            unpack2(a, e0, e1);
            u64 pp = pack2(ex2f(e0), ex2f(e1));   // (p1, p2)
            l12 = add2(l12, pp);

            G[0]  = fma2(pp, fd0,  G[0]);
            G[1]  = fma2(pp, fd1,  G[1]);
            G[2]  = fma2(pp, fd2,  G[2]);
            G[3]  = fma2(pp, fd3,  G[3]);
            G[4]  = fma2(pp, fd4,  G[4]);
            G[5]  = fma2(pp, fd5,  G[5]);
            G[6]  = fma2(pp, fd6,  G[6]);
            G[7]  = fma2(pp, fd7,  G[7]);
            G[8]  = fma2(pp, fd8,  G[8]);
            G[9]  = fma2(pp, fd9,  G[9]);
            G[10] = fma2(pp, fd10, G[10]);
            G[11] = fma2(pp, fd11, G[11]);
        }

        // epilogue: outD[o] += inv ⊙ Σ_c G[c]·Pp[h][o][c]   (lanes stay branches)
        float l1, l2;
        unpack2(l12, l1, l2);
        u64 invD = pack2(rcpf(l1), rcpf(l2));
#pragma unroll
        for (int o = 0; o < 6; o++) {
            u64 t = mul2(G[0], sp.Pp[h][o][0]);
#pragma unroll
            for (int c = 1; c < 12; c++) t = fma2(G[c], sp.Pp[h][o][c], t);
            outaccD[o] = fma2(t, invD, outaccD[o]);
        }
    }

#pragma unroll
    for (int o = 0; o < 6; o++) {
        float lo, hi;
        unpack2(outaccD[o], lo, hi);
        out[base + o * 16384] = sp.C[o] + lo + hi;
    }
}

// ----------------------------------------------------------------------------
extern "C" void kernel_launch(void* const* d_in, const int* in_sizes, int n_in,
                              void* d_out, int out_size)
{
    const float* img1   = (const float*)d_in[0];
    const float* img2   = (const float*)d_in[1];
    const float* W_emb  = (const float*)d_in[2];
    const float* b_emb  = (const float*)d_in[3];
    const float* W_emb2 = (const float*)d_in[4];
    const float* b_emb2 = (const float*)d_in[5];
    const float* Wq     = (const float*)d_in[6];
    const float* bq     = (const float*)d_in[7];
    const float* Wk     = (const float*)d_in[8];
    const float* bk     = (const float*)d_in[9];
    const float* Wv     = (const float*)d_in[10];
    const float* bv     = (const float*)d_in[11];
    const float* Wp     = (const float*)d_in[12];
    const float* bp     = (const float*)d_in[13];
    float* out = (float*)d_out;

    fold_partial<<<24, 512>>>(W_emb, b_emb, W_emb2, b_emb2, Wq, Wk, Wv);
    fold_reduce<<<78, 256>>>(bq, bk, bv);
    precompute_small<<<5, 256>>>(Wp, bp);
    cross_attn_main<<<512, 256>>>(img1, img2, out);
}

// round 12
// speedup vs baseline: 1.0239x; 1.0239x over previous
#include <cuda_runtime.h>

// ----------------------------------------------------------------------------
// Cross_MultiAttention — algebraically folded, dual-lane (branch-pair) f32x2.
//
// logit_h,br(s,j) = (f_br[s] @ M_h + v_h) . fcat[j]    (M_h [6,12])
// att@V folds through Wp into per-(head,branch) [6,12] P (lane-packed Pp).
// Structure = R3 (best measured): fcat lane-duplicated in smem, 2 heads per
// pass so the 6 LDS.128/j are amortized (3 per head); per head 12 fma2 logit
// (branches in lanes) + 12 fma2 dual-G + 1 l-add2 — minimal slot count.
// Key change: 1 CTA/SM with UNCAPPED registers + unroll 4 — per-warp ILP is
// the binding resource (R3 at 8 warps beat every 16-warp config).
// ----------------------------------------------------------------------------

#define SCALE_EMB 0.044194173824159216f   // 512^-0.5
#define LOG2E     1.4426950408889634f

typedef unsigned long long u64;

struct Params {
    float M[8][6][12];      // LOG2E*SCALE * A_q_h @ A_k_h^T
    float v[8][12];         // LOG2E*SCALE * bq_eff_h @ A_k_h^T
    u64   Pp[8][6][12];     // pack2(P_br1[h][o][c], P_br2[h][o][c])
    float C[6];             // bp + (Wp1+Wp2) @ bv_eff
};

__device__ float g_part[3][8][13][512];   // per-m-chunk partial folds (row12 = bias)
__device__ float g_A[3][13][512];         // folded: [0]=Aq(6)+bqe, [1]=Ak+bke, [2]=Av+bve
__device__ Params g_params;

// ---- packed f32x2 helpers ----
__device__ __forceinline__ u64 pack2(float lo, float hi) {
    u64 r; asm("mov.b64 %0, {%1,%2};" : "=l"(r) : "f"(lo), "f"(hi)); return r;
}
__device__ __forceinline__ void unpack2(u64 v, float& lo, float& hi) {
    asm("mov.b64 {%0,%1}, %2;" : "=f"(lo), "=f"(hi) : "l"(v));
}
__device__ __forceinline__ u64 fma2(u64 a, u64 b, u64 c) {
    u64 d; asm("fma.rn.f32x2 %0, %1, %2, %3;" : "=l"(d) : "l"(a), "l"(b), "l"(c)); return d;
}
__device__ __forceinline__ u64 mul2(u64 a, u64 b) {
    u64 d; asm("mul.rn.f32x2 %0, %1, %2;" : "=l"(d) : "l"(a), "l"(b)); return d;
}
__device__ __forceinline__ u64 add2(u64 a, u64 b) {
    u64 d; asm("add.rn.f32x2 %0, %1, %2;" : "=l"(d) : "l"(a), "l"(b)); return d;
}
__device__ __forceinline__ float ex2f(float x) {
    float y; asm("ex2.approx.ftz.f32 %0, %1;" : "=f"(y) : "f"(x)); return y;
}
__device__ __forceinline__ float rcpf(float x) {
    float y; asm("rcp.approx.ftz.f32 %0, %1;" : "=f"(y) : "f"(x)); return y;
}

// ----------------------------------------------------------------------------
// Precompute 1a: partial fold over a 64-wide m chunk.
// ----------------------------------------------------------------------------
__global__ void fold_partial(const float* __restrict__ W_emb,  const float* __restrict__ b_emb,
                             const float* __restrict__ W_emb2, const float* __restrict__ b_emb2,
                             const float* __restrict__ Wq, const float* __restrict__ Wk,
                             const float* __restrict__ Wv)
{
    int mat = blockIdx.x >> 3, chunk = blockIdx.x & 7;
    const float* We = (mat == 0) ? W_emb : W_emb2;
    const float* be = (mat == 0) ? b_emb : b_emb2;
    const float* W  = (mat == 0) ? Wq : (mat == 1 ? Wk : Wv);
    int R = (mat == 0) ? 6 : 12;

    __shared__ float sE[12][64];
    __shared__ float sb[64];
    int tid = threadIdx.x;
    int mc0 = chunk * 64;
    for (int i = tid; i < R * 64; i += 512) {
        int k = i >> 6, mm = i & 63;
        sE[k][mm] = We[k * 512 + mc0 + mm];
    }
    if (tid < 64) sb[tid] = be[mc0 + tid];
    __syncthreads();

    int e = tid;
    float acc[12];
#pragma unroll
    for (int k = 0; k < 12; k++) acc[k] = 0.f;
    float bacc = 0.f;
    if (R == 6) {
#pragma unroll 8
        for (int mm = 0; mm < 64; mm++) {
            float w = W[(mc0 + mm) * 512 + e];
            bacc += sb[mm] * w;
#pragma unroll
            for (int k = 0; k < 6; k++) acc[k] += sE[k][mm] * w;
        }
    } else {
#pragma unroll 4
        for (int mm = 0; mm < 64; mm++) {
            float w = W[(mc0 + mm) * 512 + e];
            bacc += sb[mm] * w;
#pragma unroll
            for (int k = 0; k < 12; k++) acc[k] += sE[k][mm] * w;
        }
    }
    for (int k = 0; k < R; k++) g_part[mat][chunk][k][e] = acc[k];
    g_part[mat][chunk][12][e] = bacc;
}

// ----------------------------------------------------------------------------
// Precompute 1b: deterministic reduce over the 8 chunks + add projection bias.
// ----------------------------------------------------------------------------
__global__ void fold_reduce(const float* __restrict__ bq, const float* __restrict__ bk,
                            const float* __restrict__ bv)
{
    int t = blockIdx.x * blockDim.x + threadIdx.x;
    if (t >= 3 * 13 * 512) return;
    int mat = t / (13 * 512);
    int r   = (t / 512) % 13;
    int e   = t & 511;
    if (mat == 0 && r >= 6 && r < 12) { g_A[0][r][e] = 0.f; return; }
    float s = 0.f;
#pragma unroll
    for (int c = 0; c < 8; c++) s += g_part[mat][c][r][e];
    if (r == 12) s += (mat == 0 ? bq[e] : (mat == 1 ? bk[e] : bv[e]));
    g_A[mat][r][e] = s;
}

// ----------------------------------------------------------------------------
// Precompute 2: tiny per-head matrices (log2e*SCALE prefolded; P lane-packed).
// ----------------------------------------------------------------------------
__global__ void precompute_small(const float* __restrict__ Wp, const float* __restrict__ bp)
{
    int idx = blockIdx.x * 256 + threadIdx.x;
    const float KS = LOG2E * SCALE_EMB;
    if (idx < 576) {                                   // M[h][k][c]
        int h = idx / 72, r = idx % 72, k = r / 12, c = r % 12;
        float s = 0.f;
#pragma unroll 4
        for (int d = 0; d < 64; d++) s += g_A[0][k][h * 64 + d] * g_A[1][c][h * 64 + d];
        g_params.M[h][k][c] = KS * s;
    } else if (idx < 672) {                            // v[h][c]
        int t = idx - 576, h = t / 12, c = t % 12;
        float s = 0.f;
#pragma unroll 4
        for (int d = 0; d < 64; d++) s += g_A[0][12][h * 64 + d] * g_A[1][c][h * 64 + d];
        g_params.v[h][c] = KS * s;
    } else if (idx < 1248) {                           // Pp[h][o][c] (both branches)
        int t = idx - 672, h = t / 72, q = t % 72, o = q / 12, c = q % 12;
        float s0 = 0.f, s1 = 0.f;
#pragma unroll 4
        for (int d = 0; d < 64; d++) {
            float av = g_A[2][c][h * 64 + d];
            s0 += Wp[o * 1024 +       h * 64 + d] * av;
            s1 += Wp[o * 1024 + 512 + h * 64 + d] * av;
        }
        g_params.Pp[h][o][c] = pack2(s0, s1);
    } else if (idx < 1254) {                           // C[o]
        int o = idx - 1248;
        float s = bp[o];
#pragma unroll 4
        for (int e = 0; e < 512; e++)
            s += (Wp[o * 1024 + e] + Wp[o * 1024 + 512 + e]) * g_A[2][12][e];
        g_params.C[o] = s;
    }
}

// ----------------------------------------------------------------------------
// Main fused kernel: one CTA per 16x16 tile (512 CTAs), one thread per query s.
// 4 passes x 2 heads; branches ride the f32x2 lanes. 1 CTA/SM, regs uncapped.
// ----------------------------------------------------------------------------
__global__ __launch_bounds__(256, 1)
void cross_attn_main(const float* __restrict__ img1, const float* __restrict__ img2,
                     float* __restrict__ out)
{
    __shared__ __align__(16) u64 sFd[256][12];   // fcat dup-lane: (f_c, f_c)
    __shared__ Params sp;

    int b  = blockIdx.x;
    int bi = b >> 6, th = (b >> 3) & 7, tw = b & 7;
    int s  = threadIdx.x;
    int y  = s >> 4, x = s & 15;
    int base = bi * 6 * 16384 + (th * 16 + y) * 128 + (tw * 16 + x);

    float f1r[6], f2r[6];
#pragma unroll
    for (int c = 0; c < 6; c++) {
        f1r[c] = img1[base + c * 16384];
        f2r[c] = img2[base + c * 16384];
    }
#pragma unroll
    for (int c = 0; c < 6; c++) {
        sFd[s][c]     = pack2(f1r[c], f1r[c]);
        sFd[s][6 + c] = pack2(f2r[c], f2r[c]);
    }
    {
        float* dst = (float*)&sp;
        const float* src = (const float*)&g_params;
        for (int i = s; i < (int)(sizeof(Params) / 4); i += 256) dst[i] = src[i];
    }
    __syncthreads();

    u64 outaccD[6];
#pragma unroll
    for (int o = 0; o < 6; o++) outaccD[o] = 0ull;

    for (int hp = 0; hp < 4; hp++) {
        const int h0 = 2 * hp, h1 = h0 + 1;

        // g[c] = (v + f_br @ M) for both heads, branches in lanes (prescaled)
        u64 g0[12], g1[12];
#pragma unroll
        for (int c = 0; c < 12; c++) {
            float a1 = sp.v[h0][c], a2 = a1;
            float b1 = sp.v[h1][c], b2 = b1;
#pragma unroll
            for (int k = 0; k < 6; k++) {
                float m0 = sp.M[h0][k][c], m1 = sp.M[h1][k][c];
                a1 += f1r[k] * m0;  a2 += f2r[k] * m0;
                b1 += f1r[k] * m1;  b2 += f2r[k] * m1;
            }
            g0[c] = pack2(a1, a2);
            g1[c] = pack2(b1, b2);
        }

        u64 G0[12], G1[12];
#pragma unroll
        for (int c = 0; c < 12; c++) { G0[c] = 0ull; G1[c] = 0ull; }
        u64 l0 = 0ull, l1 = 0ull;

        // Logits are O(0.1) by construction (weights 0.02, folded twice):
        // exp without max-subtraction is exact softmax.
#pragma unroll 4
        for (int j = 0; j < 256; j++) {
            const ulonglong2* rp = (const ulonglong2*)(&sFd[j][0]);
            ulonglong2 q0 = rp[0], q1 = rp[1], q2 = rp[2];
            ulonglong2 q3 = rp[3], q4 = rp[4], q5 = rp[5];
            u64 fd0 = q0.x, fd1 = q0.y, fd2  = q1.x, fd3  = q1.y;
            u64 fd4 = q2.x, fd5 = q2.y, fd6  = q3.x, fd7  = q3.y;
            u64 fd8 = q4.x, fd9 = q4.y, fd10 = q5.x, fd11 = q5.y;

            // dual-lane logits, two heads: two 6-deep chains per head
            u64 ae = mul2(g0[0], fd0);
            u64 ao = mul2(g0[1], fd1);
            u64 be = mul2(g1[0], fd0);
            u64 bo = mul2(g1[1], fd1);
            ae = fma2(g0[2],  fd2,  ae);  ao = fma2(g0[3],  fd3,  ao);
            be = fma2(g1[2],  fd2,  be);  bo = fma2(g1[3],  fd3,  bo);
            ae = fma2(g0[4],  fd4,  ae);  ao = fma2(g0[5],  fd5,  ao);
            be = fma2(g1[4],  fd4,  be);  bo = fma2(g1[5],  fd5,  bo);
            ae = fma2(g0[6],  fd6,  ae);  ao = fma2(g0[7],  fd7,  ao);
            be = fma2(g1[6],  fd6,  be);  bo = fma2(g1[7],  fd7,  bo);
            ae = fma2(g0[8],  fd8,  ae);  ao = fma2(g0[9],  fd9,  ao);
            be = fma2(g1[8],  fd8,  be);  bo = fma2(g1[9],  fd9,  bo);
            ae = fma2(g0[10], fd10, ae);  ao = fma2(g0[11], fd11, ao);
            be = fma2(g1[10], fd10, be);  bo = fma2(g1[11], fd11, bo);
            u64 a0 = add2(ae, ao);        // (l_br1, l_br2) head0
            u64 a1 = add2(be, bo);        // head1

            float e0, e1;
            unpack2(a0, e0, e1);
            u64 pp0 = pack2(ex2f(e0), ex2f(e1));
            unpack2(a1, e0, e1);
            u64 pp1 = pack2(ex2f(e0), ex2f(e1));
            l0 = add2(l0, pp0);
            l1 = add2(l1, pp1);

            G0[0]  = fma2(pp0, fd0,  G0[0]);   G1[0]  = fma2(pp1, fd0,  G1[0]);
            G0[1]  = fma2(pp0, fd1,  G0[1]);   G1[1]  = fma2(pp1, fd1,  G1[1]);
            G0[2]  = fma2(pp0, fd2,  G0[2]);   G1[2]  = fma2(pp1, fd2,  G1[2]);
            G0[3]  = fma2(pp0, fd3,  G0[3]);   G1[3]  = fma2(pp1, fd3,  G1[3]);
            G0[4]  = fma2(pp0, fd4,  G0[4]);   G1[4]  = fma2(pp1, fd4,  G1[4]);
            G0[5]  = fma2(pp0, fd5,  G0[5]);   G1[5]  = fma2(pp1, fd5,  G1[5]);
            G0[6]  = fma2(pp0, fd6,  G0[6]);   G1[6]  = fma2(pp1, fd6,  G1[6]);
            G0[7]  = fma2(pp0, fd7,  G0[7]);   G1[7]  = fma2(pp1, fd7,  G1[7]);
            G0[8]  = fma2(pp0, fd8,  G0[8]);   G1[8]  = fma2(pp1, fd8,  G1[8]);
            G0[9]  = fma2(pp0, fd9,  G0[9]);   G1[9]  = fma2(pp1, fd9,  G1[9]);
            G0[10] = fma2(pp0, fd10, G0[10]);  G1[10] = fma2(pp1, fd10, G1[10]);
            G0[11] = fma2(pp0, fd11, G0[11]);  G1[11] = fma2(pp1, fd11, G1[11]);
        }

        // epilogue: outD[o] += inv ⊙ Σ_c G[c]·Pp[h][o][c]  (lanes = branches)
        float la, lb;
        unpack2(l0, la, lb);
        u64 inv0 = pack2(rcpf(la), rcpf(lb));
        unpack2(l1, la, lb);
        u64 inv1 = pack2(rcpf(la), rcpf(lb));
#pragma unroll
        for (int o = 0; o < 6; o++) {
            u64 t0 = mul2(G0[0], sp.Pp[h0][o][0]);
            u64 t1 = mul2(G1[0], sp.Pp[h1][o][0]);
#pragma unroll
            for (int c = 1; c < 12; c++) {
                t0 = fma2(G0[c], sp.Pp[h0][o][c], t0);
                t1 = fma2(G1[c], sp.Pp[h1][o][c], t1);
            }
            outaccD[o] = fma2(t0, inv0, outaccD[o]);
            outaccD[o] = fma2(t1, inv1, outaccD[o]);
        }
    }

#pragma unroll
    for (int o = 0; o < 6; o++) {
        float lo, hi;
        unpack2(outaccD[o], lo, hi);
        out[base + o * 16384] = sp.C[o] + lo + hi;
    }
}

// ----------------------------------------------------------------------------
extern "C" void kernel_launch(void* const* d_in, const int* in_sizes, int n_in,
                              void* d_out, int out_size)
{
    const float* img1   = (const float*)d_in[0];
    const float* img2   = (const float*)d_in[1];
    const float* W_emb  = (const float*)d_in[2];
    const float* b_emb  = (const float*)d_in[3];
    const float* W_emb2 = (const float*)d_in[4];
    const float* b_emb2 = (const float*)d_in[5];
    const float* Wq     = (const float*)d_in[6];
    const float* bq     = (const float*)d_in[7];
    const float* Wk     = (const float*)d_in[8];
    const float* bk     = (const float*)d_in[9];
    const float* Wv     = (const float*)d_in[10];
    const float* bv     = (const float*)d_in[11];
    const float* Wp     = (const float*)d_in[12];
    const float* bp     = (const float*)d_in[13];
    float* out = (float*)d_out;

    fold_partial<<<24, 512>>>(W_emb, b_emb, W_emb2, b_emb2, Wq, Wk, Wv);
    fold_reduce<<<78, 256>>>(bq, bk, bv);
    precompute_small<<<5, 256>>>(Wp, bp);
    cross_attn_main<<<512, 256>>>(img1, img2, out);
}